// round 7
// baseline (speedup 1.0000x reference)
#include <cuda_runtime.h>
#include <cuda_bf16.h>

// MLLoss: per-sample hinge loss over [B,16] f32 distances -> scalar mean.
// Labels int32. HBM-bound: 288 MB read.
//
// R7: fully coalesced distance loads (4x contiguous LDG.128 per warp-iter,
// 4 lines each instead of 16) + BALLOT-based label routing:
//   one coalesced label load per array, then 3 ballots give every lane
//   bitmask access to any row's gate -- no shuffles, no redundant gathers.
// Loss decomposition: total = sum (dl<=1)*chunk_hinge + sum rowterm,
// rowterm computed by the lane holding cols 0..3 from its own registers.

#define THREADS 256
#define BLOCKS  1216   // 8 blocks/SM x 152 SMs = one full wave

__device__ float        g_partial;   // zero at load; reset by last block each call
__device__ unsigned int g_count;

__global__ __launch_bounds__(THREADS, 8)
void mlloss_kernel(const float4* __restrict__ dist4,  // [B,16] as B*4 float4
                   const int* __restrict__ doctor,    // [B] int32 {0,1,2}
                   const int* __restrict__ real_l,    // [B] int32 {0,1}
                   float* __restrict__ out,
                   int B, float inv_B)
{
    const int lane     = threadIdx.x & 31;
    const bool is_c0   = (lane & 3) == 0;   // holds cols 0..3 of its row
    const int row_off  = lane >> 2;         // row within 8-row group (0..7)

    const int warp_id   = (blockIdx.x * blockDim.x + threadIdx.x) >> 5;
    const int num_warps = (gridDim.x * blockDim.x) >> 5;
    const int nchunks   = B >> 5;            // 32 rows per warp-iteration

    float acc = 0.0f;

    for (int it = warp_id; it < nchunks; it += num_warps) {
        const int row_base = it << 5;
        const size_t f4    = (size_t)row_base << 2;   // 128 float4, 2KB contiguous

        // coalesced label loads: lane i holds labels of row row_base+i
        const int dl_me = __ldcs(&doctor[row_base + lane]);
        const int rl_me = __ldcs(&real_l[row_base + lane]);

        // contiguous distance loads: 512B per LDG.128 (4 lines, 0 waste)
        float4 v[4];
        #pragma unroll
        for (int u = 0; u < 4; u++)
            v[u] = __ldcs(&dist4[f4 + u * 32 + lane]);

        // label bitmasks: bit r = predicate for row row_base+r
        const unsigned b0 = __ballot_sync(0xFFFFFFFFu, dl_me == 0);
        const unsigned b1 = __ballot_sync(0xFFFFFFFFu, dl_me == 1);
        const unsigned br = __ballot_sync(0xFFFFFFFFu, rl_me == 0);
        const unsigned g  = b0 | b1;          // dl <= 1 : hinge-sum gate

        #pragma unroll
        for (int u = 0; u < 4; u++) {
            const float4 x = v[u];
            const float h0 = fmaxf(1.0f - x.x, 0.0f);
            const float h1 = fmaxf(1.0f - x.y, 0.0f);
            const float h2 = fmaxf(1.0f - x.z, 0.0f);
            const float h3 = fmaxf(1.0f - x.w, 0.0f);
            const float s  = (h0 + h1) + (h2 + h3);

            const int idx = u * 8 + row_off;  // this lane's row within the 32

            // hinge-sum contribution for rows with dl in {0,1}
            acc += ((g >> idx) & 1u) ? s : 0.0f;

            // row-specific term: only the lane holding columns 0..3
            if (is_c0) {
                const bool d0 = (b0 >> idx) & 1u;
                const bool d1 = (b1 >> idx) & 1u;
                const bool r0 = (br >> idx) & 1u;
                acc += d0 ? (x.x - h0)
                     : d1 ? (x.y - h1)
                          : (r0 ? h1 : h0);
            }
        }
    }

    // tail rows (B % 32) -- scalar, block 0 only
    const int tail_start = nchunks << 5;
    if (blockIdx.x == 0) {
        for (int row = tail_start + threadIdx.x; row < B; row += blockDim.x) {
            const size_t base = (size_t)row * 4;
            const float4 a = dist4[base + 0], b = dist4[base + 1];
            const float4 c = dist4[base + 2], d = dist4[base + 3];
            const float h0 = fmaxf(1.0f - a.x, 0.0f);
            const float h1 = fmaxf(1.0f - a.y, 0.0f);
            float hs = h0 + h1
                     + fmaxf(1.0f - a.z, 0.0f) + fmaxf(1.0f - a.w, 0.0f)
                     + fmaxf(1.0f - b.x, 0.0f) + fmaxf(1.0f - b.y, 0.0f)
                     + fmaxf(1.0f - b.z, 0.0f) + fmaxf(1.0f - b.w, 0.0f)
                     + fmaxf(1.0f - c.x, 0.0f) + fmaxf(1.0f - c.y, 0.0f)
                     + fmaxf(1.0f - c.z, 0.0f) + fmaxf(1.0f - c.w, 0.0f)
                     + fmaxf(1.0f - d.x, 0.0f) + fmaxf(1.0f - d.y, 0.0f)
                     + fmaxf(1.0f - d.z, 0.0f) + fmaxf(1.0f - d.w, 0.0f);
            const int dlv = doctor[row], rlv = real_l[row];
            acc += (dlv == 0) ? (a.x + hs - h0)
                 : (dlv == 1) ? (a.y + hs - h1)
                              : ((rlv == 0) ? h1 : h0);
        }
    }

    // warp reduce
    #pragma unroll
    for (int off = 16; off > 0; off >>= 1)
        acc += __shfl_xor_sync(0xFFFFFFFFu, acc, off);

    __shared__ float warp_sums[THREADS / 32];
    const int wid = threadIdx.x >> 5;
    if (lane == 0) warp_sums[wid] = acc;
    __syncthreads();

    if (wid == 0) {
        float vsum = (lane < THREADS / 32) ? warp_sums[lane] : 0.0f;
        #pragma unroll
        for (int off = 16; off > 0; off >>= 1)
            vsum += __shfl_xor_sync(0xFFFFFFFFu, vsum, off);

        if (lane == 0) {
            atomicAdd(&g_partial, vsum);
            __threadfence();
            const unsigned int ticket = atomicAdd(&g_count, 1u);
            if (ticket == gridDim.x - 1) {
                const float total = atomicAdd(&g_partial, 0.0f); // fenced read
                out[0] = total * inv_B;
                g_partial = 0.0f;
                g_count   = 0u;
                __threadfence();
            }
        }
    }
}

extern "C" void kernel_launch(void* const* d_in, const int* in_sizes, int n_in,
                              void* d_out, int out_size)
{
    const float4* dist4  = (const float4*)d_in[0];
    const int*    doctor = (const int*)d_in[1];
    const int*    real_l = (const int*)d_in[2];
    float*        out    = (float*)d_out;

    const int B = in_sizes[1];
    const float inv_B = 1.0f / (float)B;

    mlloss_kernel<<<BLOCKS, THREADS>>>(dist4, doctor, real_l, out, B, inv_B);
}

// round 8
// speedup vs baseline: 1.0334x; 1.0334x over previous
#include <cuda_runtime.h>
#include <cuda_bf16.h>

// MLLoss: per-sample hinge loss over [B,16] f32 distances -> scalar mean.
// Labels int32. HBM-bound.
//
// R8 = R6 (best: 49.6us, DRAM 79.8% = effective ceiling) + BYTE REDUCTION:
// rows with doctor==2 (1/3 of rows) only need cols 0..1. A row is two 32B
// DRAM sectors (cols 0-7 | cols 8-15); skipping the loads of cols 8-15 for
// dl==2 lanes drops ~42MB of the 288MB (L1 is sector-granular, predicated
// lanes fetch nothing). Labels software-pipelined one iteration ahead so the
// branch never waits on the label load.

#define THREADS 256
#define BLOCKS  1216   // 8 blocks/SM x 152 SMs = one full wave

__device__ float        g_partial;   // zero at load; reset by last block each call
__device__ unsigned int g_count;

__global__ __launch_bounds__(THREADS, 8)
void mlloss_kernel(const float4* __restrict__ dist4,  // [B,16] as B*4 float4
                   const int* __restrict__ doctor,    // [B] int32 {0,1,2}
                   const int* __restrict__ real_l,    // [B] int32 {0,1}
                   float* __restrict__ out,
                   int B, float inv_B)
{
    const int tid    = blockIdx.x * blockDim.x + threadIdx.x;
    const int stride = gridDim.x * blockDim.x;

    float acc = 0.0f;

    int row = tid;
    int dl = 0, rl = 0;
    if (row < B) {                       // prime the label pipeline
        dl = __ldcs(&doctor[row]);
        rl = __ldcs(&real_l[row]);
    }

    while (row < B) {
        const int nrow = row + stride;
        int ndl = 0, nrl = 0;
        if (nrow < B) {                  // prefetch next iteration's labels
            ndl = __ldcs(&doctor[nrow]);
            nrl = __ldcs(&real_l[nrow]);
        }

        const size_t base = (size_t)row * 4;
        // sector 0 (cols 0-7): always fetched
        const float4 a = __ldcs(&dist4[base + 0]);
        const float4 b = __ldcs(&dist4[base + 1]);

        const float h0 = fmaxf(1.0f - a.x, 0.0f);
        const float h1 = fmaxf(1.0f - a.y, 0.0f);

        float loss;
        if (dl <= 1) {
            // sector 1 (cols 8-15): only for doctor in {0,1}
            const float4 c = __ldcs(&dist4[base + 2]);
            const float4 d = __ldcs(&dist4[base + 3]);

            float hs = h0 + h1
                     + fmaxf(1.0f - a.z, 0.0f) + fmaxf(1.0f - a.w, 0.0f)
                     + fmaxf(1.0f - b.x, 0.0f) + fmaxf(1.0f - b.y, 0.0f)
                     + fmaxf(1.0f - b.z, 0.0f) + fmaxf(1.0f - b.w, 0.0f)
                     + fmaxf(1.0f - c.x, 0.0f) + fmaxf(1.0f - c.y, 0.0f)
                     + fmaxf(1.0f - c.z, 0.0f) + fmaxf(1.0f - c.w, 0.0f)
                     + fmaxf(1.0f - d.x, 0.0f) + fmaxf(1.0f - d.y, 0.0f)
                     + fmaxf(1.0f - d.z, 0.0f) + fmaxf(1.0f - d.w, 0.0f);

            loss = (dl == 0) ? (a.x + hs - h0) : (a.y + hs - h1);
        } else {
            loss = (rl == 0) ? h1 : h0;
        }
        acc += loss;

        row = nrow;
        dl  = ndl;
        rl  = nrl;
    }

    // warp reduce
    #pragma unroll
    for (int off = 16; off > 0; off >>= 1)
        acc += __shfl_xor_sync(0xFFFFFFFFu, acc, off);

    __shared__ float warp_sums[THREADS / 32];
    const int lane = threadIdx.x & 31;
    const int wid  = threadIdx.x >> 5;
    if (lane == 0) warp_sums[wid] = acc;
    __syncthreads();

    if (wid == 0) {
        float v = (lane < THREADS / 32) ? warp_sums[lane] : 0.0f;
        #pragma unroll
        for (int off = 16; off > 0; off >>= 1)
            v += __shfl_xor_sync(0xFFFFFFFFu, v, off);

        if (lane == 0) {
            atomicAdd(&g_partial, v);
            __threadfence();
            const unsigned int ticket = atomicAdd(&g_count, 1u);
            if (ticket == gridDim.x - 1) {
                const float total = atomicAdd(&g_partial, 0.0f); // fenced read
                out[0] = total * inv_B;
                g_partial = 0.0f;
                g_count   = 0u;
                __threadfence();
            }
        }
    }
}

extern "C" void kernel_launch(void* const* d_in, const int* in_sizes, int n_in,
                              void* d_out, int out_size)
{
    const float4* dist4  = (const float4*)d_in[0];
    const int*    doctor = (const int*)d_in[1];
    const int*    real_l = (const int*)d_in[2];
    float*        out    = (float*)d_out;

    const int B = in_sizes[1];
    const float inv_B = 1.0f / (float)B;

    mlloss_kernel<<<BLOCKS, THREADS>>>(dist4, doctor, real_l, out, B, inv_B);
}